// round 13
// baseline (speedup 1.0000x reference)
#include <cuda_runtime.h>
#include <cuda_bf16.h>
#include <cstdint>
#include <cstddef>

#define B_  32
#define T_  2048
#define D_  512
#define L_  512
#define NG  2048          // 3L gate cols + L candidate cols
#define GW  1536          // w_w column count

// Scratch: precomputed x-part of preactivations (+bias), and bf16 split copies.
__device__ float g_pre[(size_t)B_ * T_ * NG];
__device__ __nv_bfloat16 g_xhi[(size_t)B_ * T_ * D_];
__device__ __nv_bfloat16 g_xlo[(size_t)B_ * T_ * D_];
__device__ __nv_bfloat16 g_whi[(size_t)NG * D_];   // W^T [n][k], ww+mw merged
__device__ __nv_bfloat16 g_wlo[(size_t)NG * D_];

#define NCTA 128
__device__ unsigned int g_flags[NCTA * 8];
__device__ float g_hbuf[2 * L_ * B_];

__device__ __forceinline__ unsigned ld_acq(const unsigned* p) {
    unsigned v;
    asm volatile("ld.acquire.gpu.global.u32 %0, [%1];" : "=r"(v) : "l"(p));
    return v;
}
__device__ __forceinline__ void st_rel(unsigned* p, unsigned v) {
    asm volatile("st.release.gpu.global.u32 [%0], %1;" :: "l"(p), "r"(v));
}

// ---------------------------------------------------------------------------
// Prep kernels: split fp32 -> bf16 hi/lo
// ---------------------------------------------------------------------------
__global__ __launch_bounds__(256)
void convx_kernel(const float* __restrict__ x)
{
    size_t i = ((size_t)blockIdx.x * 256 + threadIdx.x) * 4;
    float4 v = *(const float4*)(x + i);
    __nv_bfloat16 h0 = __float2bfloat16(v.x);
    __nv_bfloat16 h1 = __float2bfloat16(v.y);
    __nv_bfloat16 h2 = __float2bfloat16(v.z);
    __nv_bfloat16 h3 = __float2bfloat16(v.w);
    ushort4 hs, ls;
    hs.x = __bfloat16_as_ushort(h0); hs.y = __bfloat16_as_ushort(h1);
    hs.z = __bfloat16_as_ushort(h2); hs.w = __bfloat16_as_ushort(h3);
    ls.x = __bfloat16_as_ushort(__float2bfloat16(v.x - __bfloat162float(h0)));
    ls.y = __bfloat16_as_ushort(__float2bfloat16(v.y - __bfloat162float(h1)));
    ls.z = __bfloat16_as_ushort(__float2bfloat16(v.z - __bfloat162float(h2)));
    ls.w = __bfloat16_as_ushort(__float2bfloat16(v.w - __bfloat162float(h3)));
    *(ushort4*)&g_xhi[i] = hs;
    *(ushort4*)&g_xlo[i] = ls;
}

__global__ __launch_bounds__(256)
void convw_kernel(const float* __restrict__ ww, const float* __restrict__ mw)
{
    const int tid = threadIdx.x;
    if (blockIdx.x == 0) {
        #pragma unroll
        for (int r = 0; r < 4; r++) g_flags[r * 256 + tid] = 0u;
    }
    int i = blockIdx.x * 256 + tid;        // 0 .. NG*512-1
    int n = i >> 9;
    int k = i & 511;
    float w = (n < GW) ? ww[(size_t)k * GW + n] : mw[(size_t)k * L_ + (n - GW)];
    __nv_bfloat16 h = __float2bfloat16(w);
    g_whi[(size_t)n * 512 + k] = h;
    g_wlo[(size_t)n * 512 + k] = __float2bfloat16(w - __bfloat162float(h));
}

// ---------------------------------------------------------------------------
// Phase 1 (tensor, mma.sync): PRE = X @ W_x + bias via bf16x3 split HMMA.
// 128x128 CTA tile, 8 warps (2x4) -> 64x32 per warp.
// K in 8 chunks of 64, cp.async DOUBLE-BUFFERED (chunk c+1 streams during
// compute of chunk c). Tiles padded to 72 elems/row (conflict-free LDS.32).
// ---------------------------------------------------------------------------
#define TILE_B 18432                 // 128 rows * 144 bytes
#define BUF_B  (4 * TILE_B)          // Ahi, Alo, Bhi, Blo
#define GS2_TOTAL (2 * BUF_B + 512)

#define CP16(dst, src) \
    asm volatile("cp.async.ca.shared.global [%0], [%1], 16;" :: "r"(dst), "l"(src))

__device__ __forceinline__ uint32_t smem_u32(const void* p) {
    uint32_t a;
    asm("{ .reg .u64 t; cvta.to.shared.u64 t, %1; cvt.u32.u64 %0, t; }" : "=r"(a) : "l"(p));
    return a;
}

__device__ __forceinline__ void mma16816(float* d, const uint32_t* a, const uint32_t* b) {
    asm volatile(
        "mma.sync.aligned.m16n8k16.row.col.f32.bf16.bf16.f32 "
        "{%0,%1,%2,%3}, {%4,%5,%6,%7}, {%8,%9}, {%0,%1,%2,%3};"
        : "+f"(d[0]), "+f"(d[1]), "+f"(d[2]), "+f"(d[3])
        : "r"(a[0]), "r"(a[1]), "r"(a[2]), "r"(a[3]), "r"(b[0]), "r"(b[1]));
}

__global__ __launch_bounds__(256, 1)
void gemm_mma_kernel(const float* __restrict__ wb, const float* __restrict__ mb)
{
    extern __shared__ char sm[];
    float* sBias = (float*)(sm + 2 * BUF_B);

    const int tid  = threadIdx.x;
    const int wid  = tid >> 5;
    const int lane = tid & 31;
    const int mh   = wid >> 2;
    const int nq   = wid & 3;
    const int l4   = lane >> 2;
    const int l2   = (lane & 3) * 2;
    const int n0 = blockIdx.x * 128;
    const int m0 = blockIdx.y * 128;

    uint32_t sbase = smem_u32(sm);

    if (tid < 128)
        sBias[tid] = (n0 + tid < GW) ? wb[n0 + tid] : mb[n0 + tid - GW];

    float acc[4][4][4];
    #pragma unroll
    for (int mt = 0; mt < 4; mt++)
        #pragma unroll
        for (int nt = 0; nt < 4; nt++)
            #pragma unroll
            for (int r = 0; r < 4; r++) acc[mt][nt][r] = 0.f;

    const int prow = tid >> 1;           // 0..127
    const int pk0  = (tid & 1) * 4;      // 16B-unit base within row (8 units/row)

    // prefetch helper (inline): chunk c -> buffer bsel
    #define PREFETCH(c, bsel)                                                   \
    {                                                                           \
        uint32_t dbase = sbase + (bsel) * BUF_B + prow * 144;                   \
        size_t ga = (size_t)(m0 + prow) * 512 + (c) * 64;                       \
        size_t gb = (size_t)(n0 + prow) * 512 + (c) * 64;                       \
        _Pragma("unroll")                                                       \
        for (int i = 0; i < 4; i++) {                                           \
            int kb = pk0 + i;                                                   \
            CP16(dbase + kb * 16,              (const char*)&g_xhi[ga + kb * 8]);\
            CP16(dbase + kb * 16 + TILE_B,     (const char*)&g_xlo[ga + kb * 8]);\
            CP16(dbase + kb * 16 + 2 * TILE_B, (const char*)&g_whi[gb + kb * 8]);\
            CP16(dbase + kb * 16 + 3 * TILE_B, (const char*)&g_wlo[gb + kb * 8]);\
        }                                                                       \
        asm volatile("cp.async.commit_group;" ::: "memory");                    \
    }

    PREFETCH(0, 0)

    for (int c = 0; c < 8; c++) {
        const int bsel = c & 1;
        if (c < 7) {
            PREFETCH(c + 1, bsel ^ 1)
            asm volatile("cp.async.wait_group 1;" ::: "memory");
        } else {
            asm volatile("cp.async.wait_group 0;" ::: "memory");
        }
        __syncthreads();    // chunk c resident for all warps

        const __nv_bfloat16* sAhi = (const __nv_bfloat16*)(sm + bsel * BUF_B);
        const __nv_bfloat16* sAlo = (const __nv_bfloat16*)(sm + bsel * BUF_B + TILE_B);
        const __nv_bfloat16* sBhi = (const __nv_bfloat16*)(sm + bsel * BUF_B + 2 * TILE_B);
        const __nv_bfloat16* sBlo = (const __nv_bfloat16*)(sm + bsel * BUF_B + 3 * TILE_B);

        #pragma unroll
        for (int p = 0; p < 3; p++) {
            const __nv_bfloat16* Ab = (p == 2) ? sAlo : sAhi;
            const __nv_bfloat16* Bb = (p == 1) ? sBlo : sBhi;
            #pragma unroll
            for (int ks = 0; ks < 4; ks++) {
                const int C = ks * 16;
                uint32_t bfr[4][2];
                #pragma unroll
                for (int nt = 0; nt < 4; nt++) {
                    int nr = nq * 32 + nt * 8 + l4;
                    bfr[nt][0] = *(const uint32_t*)&Bb[nr * 72 + C + l2];
                    bfr[nt][1] = *(const uint32_t*)&Bb[nr * 72 + C + 8 + l2];
                }
                #pragma unroll
                for (int mt = 0; mt < 4; mt++) {
                    int r = mh * 64 + mt * 16 + l4;
                    uint32_t af[4];
                    af[0] = *(const uint32_t*)&Ab[r * 72 + C + l2];
                    af[1] = *(const uint32_t*)&Ab[(r + 8) * 72 + C + l2];
                    af[2] = *(const uint32_t*)&Ab[r * 72 + C + 8 + l2];
                    af[3] = *(const uint32_t*)&Ab[(r + 8) * 72 + C + 8 + l2];
                    #pragma unroll
                    for (int nt = 0; nt < 4; nt++)
                        mma16816(acc[mt][nt], af, bfr[nt]);
                }
            }
        }
        __syncthreads();    // all warps done with buffer bsel before it refills
    }

    // ---- epilogue: registers + bias -> gmem ----
    #pragma unroll
    for (int mt = 0; mt < 4; mt++) {
        int gr = m0 + mh * 64 + mt * 16 + l4;
        #pragma unroll
        for (int nt = 0; nt < 4; nt++) {
            int lc = nq * 32 + nt * 8 + l2;
            float b0 = sBias[lc], b1 = sBias[lc + 1];
            float2 o0 = make_float2(acc[mt][nt][0] + b0, acc[mt][nt][1] + b1);
            float2 o1 = make_float2(acc[mt][nt][2] + b0, acc[mt][nt][3] + b1);
            *(float2*)&g_pre[(size_t)gr * NG + n0 + lc]       = o0;
            *(float2*)&g_pre[(size_t)(gr + 8) * NG + n0 + lc] = o1;
        }
    }
    #undef PREFETCH
}

// ---------------------------------------------------------------------------
// Phase 2: persistent recurrent kernel, sub-chunk pipelined handoff.
// Each warp splits its 64-K block into 4 sub-chunks of 16: poll the 4
// producers of sub s+1 and issue its LDGs into registers WHILE computing
// the FFMAs of sub s (hides poll+staging latency under the GEMM).
// Accumulation order unchanged -> numerics identical to round 12.
// ---------------------------------------------------------------------------
#define NTHR 256
#define SMEM_FLOATS (512*36 + 512*20 + 2*256*20)

__device__ __forceinline__ float sigf(float x)     { return 1.f / (1.f + __expf(-x)); }
__device__ __forceinline__ float tanh_fast(float x){ return 2.f / (1.f + __expf(-2.f * x)) - 1.f; }

__global__ __launch_bounds__(NTHR, 1)
void lstm_kernel(const float* __restrict__ h0, const float* __restrict__ c0,
                 const float* __restrict__ ww, const float* __restrict__ mw,
                 float* __restrict__ out)
{
    extern __shared__ float smem[];
    float* sH   = smem;                 // sH[k*36 + b]
    float* sW   = smem + 512 * 36;      // sW[k*20 + j]
    float* sRed = sW + 512 * 20;        // sRed[par][tid*20 + v]

    const int tid = threadIdx.x;
    const int L0  = blockIdx.x * 4;

    for (int it = tid; it < 16 * 512; it += NTHR) {
        int k = it >> 4;
        int j = it & 15;
        int g = j >> 2, jl = j & 3;
        float w;
        if (g < 3) w = ww[(size_t)(512 + k) * GW + g * 512 + L0 + jl];
        else       w = mw[(size_t)(512 + k) * L_ + L0 + jl];
        sW[k * 20 + j] = w;
    }

    const int s  = tid >> 5;
    const int u  = tid & 31;
    const int b0 = (u >> 2) * 4;
    const int j0 = (u & 3) * 4;
    const int kbase = s * 64;

    const int eb  = tid >> 2;
    const int ejl = tid & 3;
    float c_reg = 0.f;
    float pre_r[4];
    if (tid < 128) {
        c_reg = c0[eb * L_ + L0 + ejl];
        #pragma unroll
        for (int g = 0; g < 4; g++)
            pre_r[g] = g_pre[(size_t)eb * T_ * NG + g * 512 + L0 + ejl];
        g_hbuf[(L0 + ejl) * 32 + eb] = h0[eb * L_ + L0 + ejl];
    }
    __syncthreads();
    if (tid == 0) st_rel(&g_flags[blockIdx.x * 8], 1u);

    float* hid  = out;
    float* cell = out + (size_t)B_ * T_ * L_;

    // flag pointer for sub-chunk polls: lanes 0-3 poll 4 producers of a sub
    const int fbase = s * 16;
    const int srow  = u >> 3;            // row-within-4 for staging
    const int sc4   = (u & 7) * 4;       // batch offset for staging

    int par = 0;
    for (int t = 0; t < T_; t++) {
        const unsigned tgt = (unsigned)(t + 1);
        const float* buf = g_hbuf + (size_t)(t & 1) * (L_ * 32);

        // poll sub 0 and load its 4 rows into registers
        {
            const unsigned* fp = &g_flags[(fbase + u) * 8];
            for (;;) {
                unsigned v = (u < 4) ? ld_acq(fp) : 0xFFFFFFFFu;
                if (__all_sync(0xffffffffu, v >= tgt)) break;
            }
        }
        float4 pr[4];
        #pragma unroll
        for (int i = 0; i < 4; i++)
            pr[i] = *(const float4*)&buf[(kbase + i * 4 + srow) * 32 + sc4];

        float acc[4][4];
        #pragma unroll
        for (int i = 0; i < 4; i++)
            #pragma unroll
            for (int j = 0; j < 4; j++) acc[i][j] = 0.f;

        #pragma unroll
        for (int sub = 0; sub < 4; sub++) {
            float4 nx[4];
            if (sub < 3) {
                const unsigned* fp = &g_flags[(fbase + (sub + 1) * 4 + (u & 3)) * 8];
                for (;;) {
                    unsigned v = (u < 4) ? ld_acq(fp) : 0xFFFFFFFFu;
                    if (__all_sync(0xffffffffu, v >= tgt)) break;
                }
                #pragma unroll
                for (int i = 0; i < 4; i++)
                    nx[i] = *(const float4*)&buf[(kbase + (sub + 1) * 16 + i * 4 + srow) * 32 + sc4];
            }
            // stage sub's 4 rows (registers -> smem)
            #pragma unroll
            for (int i = 0; i < 4; i++)
                *(float4*)&sH[(kbase + sub * 16 + i * 4 + srow) * 36 + sc4] = pr[i];
            __syncwarp();

            // GEMM over this 16-k sub-chunk (k ascending: same order as before)
            const float* hp = sH + (kbase + sub * 16) * 36 + b0;
            const float* wp = sW + (kbase + sub * 16) * 20 + j0;
            #pragma unroll
            for (int kk = 0; kk < 16; kk++) {
                float4 hv = *(const float4*)hp;
                float4 wv = *(const float4*)wp;
                acc[0][0] += hv.x * wv.x; acc[0][1] += hv.x * wv.y;
                acc[0][2] += hv.x * wv.z; acc[0][3] += hv.x * wv.w;
                acc[1][0] += hv.y * wv.x; acc[1][1] += hv.y * wv.y;
                acc[1][2] += hv.y * wv.z; acc[1][3] += hv.y * wv.w;
                acc[2][0] += hv.z * wv.x; acc[2][1] += hv.z * wv.y;
                acc[2][2] += hv.z * wv.z; acc[2][3] += hv.z * wv.w;
                acc[3][0] += hv.w * wv.x; acc[3][1] += hv.w * wv.y;
                acc[3][2] += hv.w * wv.z; acc[3][3] += hv.w * wv.w;
                hp += 36; wp += 20;
            }
            if (sub < 3) {
                #pragma unroll
                for (int i = 0; i < 4; i++) pr[i] = nx[i];
            }
        }

        float* red = sRed + par * (256 * 20);
        #pragma unroll
        for (int i = 0; i < 4; i++) {
            float4 v = make_float4(acc[i][0], acc[i][1], acc[i][2], acc[i][3]);
            *(float4*)&red[tid * 20 + i * 4] = v;
        }
        __syncthreads();    // all partials in sRed[par]; warps 4-7 run ahead

        if (tid < 128) {
            float z[4];
            #pragma unroll
            for (int g = 0; g < 4; g++) {
                float v = 0.f;
                #pragma unroll
                for (int ss = 0; ss < 8; ss++)
                    v += red[(ss * 32 + (eb >> 2) * 4 + g) * 20 + (eb & 3) * 4 + ejl];
                z[g] = v + pre_r[g];
            }
            float ig = sigf(z[0]);
            float fg = sigf(z[1]);
            float og = sigf(z[2]);
            float mg = tanh_fast(z[3]);
            c_reg = fg * c_reg + ig * mg;
            float hn = og * tanh_fast(c_reg);
            size_t off = ((size_t)eb * T_ + t) * L_ + L0 + ejl;
            hid[off]  = hn;
            cell[off] = c_reg;
            if (t + 1 < T_) {
                float* nb = g_hbuf + (size_t)((t + 1) & 1) * (L_ * 32);
                nb[(L0 + ejl) * 32 + eb] = hn;
                #pragma unroll
                for (int g = 0; g < 4; g++)
                    pre_r[g] = g_pre[((size_t)eb * T_ + (t + 1)) * NG + g * 512 + L0 + ejl];
                asm volatile("bar.sync 1, 128;" ::: "memory");
                if (tid == 0)
                    st_rel(&g_flags[blockIdx.x * 8], (unsigned)(t + 2));
            }
        }
        par ^= 1;
    }
}

// ---------------------------------------------------------------------------
extern "C" void kernel_launch(void* const* d_in, const int* in_sizes, int n_in,
                              void* d_out, int out_size)
{
    const float* x  = (const float*)d_in[0];
    const float* h0 = (const float*)d_in[1];
    const float* c0 = (const float*)d_in[2];
    const float* ww = (const float*)d_in[3];
    const float* wb = (const float*)d_in[4];
    const float* mw = (const float*)d_in[5];
    const float* mb = (const float*)d_in[6];
    float* out = (float*)d_out;

    cudaFuncSetAttribute(gemm_mma_kernel,
                         cudaFuncAttributeMaxDynamicSharedMemorySize, GS2_TOTAL);
    cudaFuncSetAttribute(lstm_kernel,
                         cudaFuncAttributeMaxDynamicSharedMemorySize,
                         SMEM_FLOATS * (int)sizeof(float));

    convx_kernel<<<32768, 256>>>(x);
    convw_kernel<<<4096, 256>>>(ww, mw);
    gemm_mma_kernel<<<dim3(16, 512), 256, GS2_TOTAL>>>(wb, mb);
    lstm_kernel<<<NCTA, NTHR, SMEM_FLOATS * (int)sizeof(float)>>>(h0, c0, ww, mw, out);
}

// round 14
// speedup vs baseline: 1.0401x; 1.0401x over previous
#include <cuda_runtime.h>
#include <cuda_bf16.h>
#include <cstdint>
#include <cstddef>

#define B_  32
#define T_  2048
#define D_  512
#define L_  512
#define NG  2048          // 3L gate cols + L candidate cols
#define GW  1536          // w_w column count

// Scratch: precomputed x-part of preactivations (+bias), bf16 split copies.
__device__ float g_pre[(size_t)B_ * T_ * NG];
__device__ __nv_bfloat16 g_xhi[(size_t)B_ * T_ * D_];
__device__ __nv_bfloat16 g_xlo[(size_t)B_ * T_ * D_];
__device__ __nv_bfloat16 g_whi[(size_t)NG * D_];   // W^T [n][k]
__device__ __nv_bfloat16 g_wlo[(size_t)NG * D_];

#define NCTA 128
#define NWIN 16
__device__ unsigned int g_flags[NCTA * 8];     // h-publication flags
__device__ unsigned int g_windone[NWIN];       // per-128-step-window counters
__device__ float g_hbuf[2 * L_ * B_];

__device__ __forceinline__ unsigned ld_acq(const unsigned* p) {
    unsigned v;
    asm volatile("ld.acquire.gpu.global.u32 %0, [%1];" : "=r"(v) : "l"(p));
    return v;
}
__device__ __forceinline__ void st_rel(unsigned* p, unsigned v) {
    asm volatile("st.release.gpu.global.u32 [%0], %1;" :: "l"(p), "r"(v));
}
__device__ __forceinline__ void red_rel_add(unsigned* p, unsigned v) {
    asm volatile("red.release.gpu.global.add.u32 [%0], %1;" :: "l"(p), "r"(v));
}
__device__ __forceinline__ uint32_t smem_u32(const void* p) {
    uint32_t a;
    asm("{ .reg .u64 t; cvta.to.shared.u64 t, %1; cvt.u32.u64 %0, t; }" : "=r"(a) : "l"(p));
    return a;
}

// ---------------------------------------------------------------------------
// Prep kernels: split fp32 -> bf16 hi/lo
// ---------------------------------------------------------------------------
__global__ __launch_bounds__(256)
void convx_kernel(const float* __restrict__ x)
{
    size_t i = ((size_t)blockIdx.x * 256 + threadIdx.x) * 4;
    float4 v = *(const float4*)(x + i);
    __nv_bfloat16 h0 = __float2bfloat16(v.x);
    __nv_bfloat16 h1 = __float2bfloat16(v.y);
    __nv_bfloat16 h2 = __float2bfloat16(v.z);
    __nv_bfloat16 h3 = __float2bfloat16(v.w);
    ushort4 hs, ls;
    hs.x = __bfloat16_as_ushort(h0); hs.y = __bfloat16_as_ushort(h1);
    hs.z = __bfloat16_as_ushort(h2); hs.w = __bfloat16_as_ushort(h3);
    ls.x = __bfloat16_as_ushort(__float2bfloat16(v.x - __bfloat162float(h0)));
    ls.y = __bfloat16_as_ushort(__float2bfloat16(v.y - __bfloat162float(h1)));
    ls.z = __bfloat16_as_ushort(__float2bfloat16(v.z - __bfloat162float(h2)));
    ls.w = __bfloat16_as_ushort(__float2bfloat16(v.w - __bfloat162float(h3)));
    *(ushort4*)&g_xhi[i] = hs;
    *(ushort4*)&g_xlo[i] = ls;
}

__global__ __launch_bounds__(256)
void convw_kernel(const float* __restrict__ ww, const float* __restrict__ mw)
{
    const int tid = threadIdx.x;
    if (blockIdx.x == 0) {
        #pragma unroll
        for (int r = 0; r < 4; r++) g_flags[r * 256 + tid] = 0u;
        if (tid < NWIN) g_windone[tid] = 0u;
    }
    int i = blockIdx.x * 256 + tid;
    int n = i >> 9;
    int k = i & 511;
    float w = (n < GW) ? ww[(size_t)k * GW + n] : mw[(size_t)k * L_ + (n - GW)];
    __nv_bfloat16 h = __float2bfloat16(w);
    g_whi[(size_t)n * 512 + k] = h;
    g_wlo[(size_t)n * 512 + k] = __float2bfloat16(w - __bfloat162float(h));
}

// ---------------------------------------------------------------------------
// Fused persistent kernel, 512 threads:
//   warps 0-7  : BACKGROUND producer — bf16x3 HMMA phase-1 GEMM into g_pre,
//                window-by-window (window w = timesteps [128w, 128w+128)),
//                tensor pipe only, signals via g_windone[w].
//   warps 8-15 : CRITICAL recurrent LSTM (R12 logic, high-wid = arbiter
//                priority), consumes g_pre gated by g_windone.
// No __syncthreads anywhere; named barriers: 1 = epilogue(128), 2 = critical
// (256), 3 = background(256).
// ---------------------------------------------------------------------------
#define LSTM_BYTES 155648                      // 38912 floats
#define TILE_B 18432                           // 128 rows * 144 B (72 bf16 pad)
#define SMEM_TOTAL (LSTM_BYTES + 4 * TILE_B)   // 229376 B

#define CP16(dst, src) \
    asm volatile("cp.async.ca.shared.global [%0], [%1], 16;" :: "r"(dst), "l"(src))
#define BAR(id, n) asm volatile("bar.sync %0, %1;" :: "n"(id), "n"(n) : "memory")

__device__ __forceinline__ void mma16816(float* d, const uint32_t* a, const uint32_t* b) {
    asm volatile(
        "mma.sync.aligned.m16n8k16.row.col.f32.bf16.bf16.f32 "
        "{%0,%1,%2,%3}, {%4,%5,%6,%7}, {%8,%9}, {%0,%1,%2,%3};"
        : "+f"(d[0]), "+f"(d[1]), "+f"(d[2]), "+f"(d[3])
        : "r"(a[0]), "r"(a[1]), "r"(a[2]), "r"(a[3]), "r"(b[0]), "r"(b[1]));
}

__device__ __forceinline__ float sigf(float x)     { return 1.f / (1.f + __expf(-x)); }
__device__ __forceinline__ float tanh_fast(float x){ return 2.f / (1.f + __expf(-2.f * x)) - 1.f; }

__global__ __launch_bounds__(512, 1)
void fused_kernel(const float* __restrict__ h0, const float* __restrict__ c0,
                  const float* __restrict__ ww, const float* __restrict__ wb,
                  const float* __restrict__ mw, const float* __restrict__ mb,
                  float* __restrict__ out)
{
    extern __shared__ float smem[];
    const int tid = threadIdx.x;

    if (tid < 256) {
        // =================== BACKGROUND: phase-1 HMMA producer ===============
        char* bsm = (char*)smem + LSTM_BYTES;
        uint32_t bbase = smem_u32(bsm);
        const int wid  = tid >> 5;
        const int lane = tid & 31;
        const int mh   = wid >> 2;
        const int nq   = wid & 3;
        const int l4   = lane >> 2;
        const int l2   = (lane & 3) * 2;
        const int slab = blockIdx.x >> 2;      // batch b
        const int q    = blockIdx.x & 3;       // n quarter
        const int prow = tid >> 1;
        const int pk0  = (tid & 1) * 4;

        for (int w = 0; w < NWIN; w++) {
            const int m0 = slab * 2048 + w * 128;
            for (int nt = 0; nt < 4; nt++) {
                const int n0 = q * 512 + nt * 128;

                float acc[4][4][4];
                #pragma unroll
                for (int mt = 0; mt < 4; mt++)
                    #pragma unroll
                    for (int ntf = 0; ntf < 4; ntf++)
                        #pragma unroll
                        for (int r = 0; r < 4; r++) acc[mt][ntf][r] = 0.f;

                for (int c = 0; c < 8; c++) {
                    // stage chunk c (64 k) of Ahi/Alo/Bhi/Blo
                    {
                        uint32_t dbase = bbase + prow * 144;
                        size_t ga = (size_t)(m0 + prow) * 512 + c * 64;
                        size_t gb = (size_t)(n0 + prow) * 512 + c * 64;
                        #pragma unroll
                        for (int i = 0; i < 4; i++) {
                            int kb = pk0 + i;
                            CP16(dbase + kb * 16,              (const char*)&g_xhi[ga + kb * 8]);
                            CP16(dbase + kb * 16 + TILE_B,     (const char*)&g_xlo[ga + kb * 8]);
                            CP16(dbase + kb * 16 + 2 * TILE_B, (const char*)&g_whi[gb + kb * 8]);
                            CP16(dbase + kb * 16 + 3 * TILE_B, (const char*)&g_wlo[gb + kb * 8]);
                        }
                        asm volatile("cp.async.commit_group;" ::: "memory");
                        asm volatile("cp.async.wait_group 0;" ::: "memory");
                    }
                    BAR(3, 256);

                    const __nv_bfloat16* sAhi = (const __nv_bfloat16*)bsm;
                    const __nv_bfloat16* sAlo = (const __nv_bfloat16*)(bsm + TILE_B);
                    const __nv_bfloat16* sBhi = (const __nv_bfloat16*)(bsm + 2 * TILE_B);
                    const __nv_bfloat16* sBlo = (const __nv_bfloat16*)(bsm + 3 * TILE_B);
                    #pragma unroll
                    for (int p = 0; p < 3; p++) {
                        const __nv_bfloat16* Ab = (p == 2) ? sAlo : sAhi;
                        const __nv_bfloat16* Bb = (p == 1) ? sBlo : sBhi;
                        #pragma unroll
                        for (int ks = 0; ks < 4; ks++) {
                            const int C = ks * 16;
                            uint32_t bfr[4][2];
                            #pragma unroll
                            for (int ntf = 0; ntf < 4; ntf++) {
                                int nr = nq * 32 + ntf * 8 + l4;
                                bfr[ntf][0] = *(const uint32_t*)&Bb[nr * 72 + C + l2];
                                bfr[ntf][1] = *(const uint32_t*)&Bb[nr * 72 + C + 8 + l2];
                            }
                            #pragma unroll
                            for (int mt = 0; mt < 4; mt++) {
                                int r = mh * 64 + mt * 16 + l4;
                                uint32_t af[4];
                                af[0] = *(const uint32_t*)&Ab[r * 72 + C + l2];
                                af[1] = *(const uint32_t*)&Ab[(r + 8) * 72 + C + l2];
                                af[2] = *(const uint32_t*)&Ab[r * 72 + C + 8 + l2];
                                af[3] = *(const uint32_t*)&Ab[(r + 8) * 72 + C + 8 + l2];
                                #pragma unroll
                                for (int ntf = 0; ntf < 4; ntf++)
                                    mma16816(acc[mt][ntf], af, bfr[ntf]);
                            }
                        }
                    }
                    BAR(3, 256);     // compute done before buffer refill
                }

                // epilogue: bias (direct loads) + store
                float bv[4][2];
                #pragma unroll
                for (int ntf = 0; ntf < 4; ntf++) {
                    int lc = n0 + nq * 32 + ntf * 8 + l2;
                    bv[ntf][0] = (lc < GW) ? wb[lc] : mb[lc - GW];
                    bv[ntf][1] = (lc + 1 < GW) ? wb[lc + 1] : mb[lc + 1 - GW];
                }
                #pragma unroll
                for (int mt = 0; mt < 4; mt++) {
                    int gr = m0 + mh * 64 + mt * 16 + l4;
                    #pragma unroll
                    for (int ntf = 0; ntf < 4; ntf++) {
                        int lc = n0 + nq * 32 + ntf * 8 + l2;
                        float2 o0 = make_float2(acc[mt][ntf][0] + bv[ntf][0],
                                                acc[mt][ntf][1] + bv[ntf][1]);
                        float2 o1 = make_float2(acc[mt][ntf][2] + bv[ntf][0],
                                                acc[mt][ntf][3] + bv[ntf][1]);
                        *(float2*)&g_pre[(size_t)gr * NG + lc]       = o0;
                        *(float2*)&g_pre[(size_t)(gr + 8) * NG + lc] = o1;
                    }
                }
            }
            BAR(3, 256);             // all window-w stores hb-before release
            if (tid == 0) red_rel_add(&g_windone[w], 1u);
        }
        return;
    }

    // ===================== CRITICAL: recurrent LSTM (R12) ====================
    {
        const int ct = tid - 256;
        float* sH   = smem;                 // sH[k*36 + b]
        float* sW   = smem + 512 * 36;      // sW[k*20 + j]
        float* sRed = sW + 512 * 20;        // sRed[par][ct*20 + v]

        const int L0 = blockIdx.x * 4;

        for (int it = ct; it < 16 * 512; it += 256) {
            int k = it >> 4;
            int j = it & 15;
            int g = j >> 2, jl = j & 3;
            float w;
            if (g < 3) w = ww[(size_t)(512 + k) * GW + g * 512 + L0 + jl];
            else       w = mw[(size_t)(512 + k) * L_ + L0 + jl];
            sW[k * 20 + j] = w;
        }

        const int s  = ct >> 5;
        const int u  = ct & 31;
        const int b0 = (u >> 2) * 4;
        const int j0 = (u & 3) * 4;
        const int kbase = s * 64;

        const int eb  = ct >> 2;
        const int ejl = ct & 3;
        float c_reg = 0.f;
        float pre_r[4];
        if (ct < 128) {
            c_reg = c0[eb * L_ + L0 + ejl];
            g_hbuf[(L0 + ejl) * 32 + eb] = h0[eb * L_ + L0 + ejl];
        }
        BAR(2, 256);
        if (ct == 0) st_rel(&g_flags[blockIdx.x * 8], 1u);

        if (ct < 128) {
            // wait for window 0 of g_pre, then initial prefetch
            while (ld_acq(&g_windone[0]) < (unsigned)NCTA) { }
            #pragma unroll
            for (int g = 0; g < 4; g++)
                pre_r[g] = g_pre[(size_t)eb * T_ * NG + g * 512 + L0 + ejl];
        }

        float* hid  = out;
        float* cell = out + (size_t)B_ * T_ * L_;

        const unsigned* myflag = &g_flags[(s * 16 + (u & 15)) * 8];

        int par = 0;
        for (int t = 0; t < T_; t++) {
            {
                const unsigned tgt = (unsigned)(t + 1);
                for (;;) {
                    unsigned v = ld_acq(myflag);
                    if (__all_sync(0xffffffffu, v >= tgt)) break;
                }
                const float* buf = g_hbuf + (size_t)(t & 1) * (L_ * 32);
                #pragma unroll
                for (int qq = 0; qq < 16; qq++) {
                    int f = qq * 32 + u;
                    int krow = kbase + (f >> 3);
                    int c4 = (f & 7) * 4;
                    float4 v4 = *(const float4*)&buf[krow * 32 + c4];
                    *(float4*)&sH[krow * 36 + c4] = v4;
                }
                __syncwarp();
            }

            float acc[4][4];
            #pragma unroll
            for (int i = 0; i < 4; i++)
                #pragma unroll
                for (int j = 0; j < 4; j++) acc[i][j] = 0.f;

            const float* hp = sH + kbase * 36 + b0;
            const float* wp = sW + kbase * 20 + j0;
            #pragma unroll 8
            for (int kk = 0; kk < 64; kk++) {
                float4 hv = *(const float4*)hp;
                float4 wv = *(const float4*)wp;
                acc[0][0] += hv.x * wv.x; acc[0][1] += hv.x * wv.y;
                acc[0][2] += hv.x * wv.z; acc[0][3] += hv.x * wv.w;
                acc[1][0] += hv.y * wv.x; acc[1][1] += hv.y * wv.y;
                acc[1][2] += hv.y * wv.z; acc[1][3] += hv.y * wv.w;
                acc[2][0] += hv.z * wv.x; acc[2][1] += hv.z * wv.y;
                acc[2][2] += hv.z * wv.z; acc[2][3] += hv.z * wv.w;
                acc[3][0] += hv.w * wv.x; acc[3][1] += hv.w * wv.y;
                acc[3][2] += hv.w * wv.z; acc[3][3] += hv.w * wv.w;
                hp += 36; wp += 20;
            }
            float* red = sRed + par * (256 * 20);
            #pragma unroll
            for (int i = 0; i < 4; i++) {
                float4 v = make_float4(acc[i][0], acc[i][1], acc[i][2], acc[i][3]);
                *(float4*)&red[ct * 20 + i * 4] = v;
            }
            BAR(2, 256);

            if (ct < 128) {
                float z[4];
                #pragma unroll
                for (int g = 0; g < 4; g++) {
                    float v = 0.f;
                    #pragma unroll
                    for (int ss = 0; ss < 8; ss++)
                        v += red[(ss * 32 + (eb >> 2) * 4 + g) * 20 + (eb & 3) * 4 + ejl];
                    z[g] = v + pre_r[g];
                }
                float ig = sigf(z[0]);
                float fg = sigf(z[1]);
                float og = sigf(z[2]);
                float mg = tanh_fast(z[3]);
                c_reg = fg * c_reg + ig * mg;
                float hn = og * tanh_fast(c_reg);
                size_t off = ((size_t)eb * T_ + t) * L_ + L0 + ejl;
                hid[off]  = hn;
                cell[off] = c_reg;
                if (t + 1 < T_) {
                    float* nb = g_hbuf + (size_t)((t + 1) & 1) * (L_ * 32);
                    nb[(L0 + ejl) * 32 + eb] = hn;
                    // gate g_pre window availability (once per 128 steps)
                    if (((t + 1) & 127) == 0) {
                        const unsigned* wd = &g_windone[(t + 1) >> 7];
                        while (ld_acq(wd) < (unsigned)NCTA) { }
                    }
                    #pragma unroll
                    for (int g = 0; g < 4; g++)
                        pre_r[g] = g_pre[((size_t)eb * T_ + (t + 1)) * NG + g * 512 + L0 + ejl];
                    BAR(1, 128);
                    if (ct == 0)
                        st_rel(&g_flags[blockIdx.x * 8], (unsigned)(t + 2));
                }
            }
            par ^= 1;
        }
    }
}

// ---------------------------------------------------------------------------
extern "C" void kernel_launch(void* const* d_in, const int* in_sizes, int n_in,
                              void* d_out, int out_size)
{
    const float* x  = (const float*)d_in[0];
    const float* h0 = (const float*)d_in[1];
    const float* c0 = (const float*)d_in[2];
    const float* ww = (const float*)d_in[3];
    const float* wb = (const float*)d_in[4];
    const float* mw = (const float*)d_in[5];
    const float* mb = (const float*)d_in[6];
    float* out = (float*)d_out;

    cudaFuncSetAttribute(fused_kernel,
                         cudaFuncAttributeMaxDynamicSharedMemorySize, SMEM_TOTAL);

    convx_kernel<<<32768, 256>>>(x);
    convw_kernel<<<4096, 256>>>(ww, mw);
    fused_kernel<<<NCTA, 512, SMEM_TOTAL>>>(h0, c0, ww, wb, mw, mb, out);
}

// round 15
// speedup vs baseline: 1.1711x; 1.1260x over previous
#include <cuda_runtime.h>
#include <cuda_bf16.h>
#include <cstdint>
#include <cstddef>

#define B_  32
#define T_  2048
#define D_  512
#define L_  512
#define NG  2048          // 3L gate cols + L candidate cols
#define GW  1536          // w_w column count

// Scratch: precomputed x-part of preactivations (+bias), bf16 split copies.
__device__ float g_pre[(size_t)B_ * T_ * NG];
__device__ __nv_bfloat16 g_xhi[(size_t)B_ * T_ * D_];
__device__ __nv_bfloat16 g_xlo[(size_t)B_ * T_ * D_];
__device__ __nv_bfloat16 g_whi[(size_t)NG * D_];   // W^T [n][k]
__device__ __nv_bfloat16 g_wlo[(size_t)NG * D_];

#define NCTA 128          // critical CTAs (l-split)
#define NBG  24           // dedicated background CTAs
#define GRID (NCTA + NBG)
#define NWIN 16
#define NUNITS 8192       // 512 m-tiles x 16 n-tiles
#define WIN_TILES 512u    // tiles per 128-step window

__device__ unsigned int g_flags[NCTA * 8];     // h-publication flags
__device__ unsigned int g_windone[NWIN];       // per-window tile counters
__device__ unsigned int g_qhead;               // tile queue head
__device__ float g_hbuf[2 * L_ * B_];

__device__ __forceinline__ unsigned ld_acq(const unsigned* p) {
    unsigned v;
    asm volatile("ld.acquire.gpu.global.u32 %0, [%1];" : "=r"(v) : "l"(p));
    return v;
}
__device__ __forceinline__ void st_rel(unsigned* p, unsigned v) {
    asm volatile("st.release.gpu.global.u32 [%0], %1;" :: "l"(p), "r"(v));
}
__device__ __forceinline__ void red_rel_add(unsigned* p, unsigned v) {
    asm volatile("red.release.gpu.global.add.u32 [%0], %1;" :: "l"(p), "r"(v));
}
__device__ __forceinline__ uint32_t smem_u32(const void* p) {
    uint32_t a;
    asm("{ .reg .u64 t; cvta.to.shared.u64 t, %1; cvt.u32.u64 %0, t; }" : "=r"(a) : "l"(p));
    return a;
}

// ---------------------------------------------------------------------------
// Prep kernels: split fp32 -> bf16 hi/lo (+ state resets in convw)
// ---------------------------------------------------------------------------
__global__ __launch_bounds__(256)
void convx_kernel(const float* __restrict__ x)
{
    size_t i = ((size_t)blockIdx.x * 256 + threadIdx.x) * 4;
    float4 v = *(const float4*)(x + i);
    __nv_bfloat16 h0 = __float2bfloat16(v.x);
    __nv_bfloat16 h1 = __float2bfloat16(v.y);
    __nv_bfloat16 h2 = __float2bfloat16(v.z);
    __nv_bfloat16 h3 = __float2bfloat16(v.w);
    ushort4 hs, ls;
    hs.x = __bfloat16_as_ushort(h0); hs.y = __bfloat16_as_ushort(h1);
    hs.z = __bfloat16_as_ushort(h2); hs.w = __bfloat16_as_ushort(h3);
    ls.x = __bfloat16_as_ushort(__float2bfloat16(v.x - __bfloat162float(h0)));
    ls.y = __bfloat16_as_ushort(__float2bfloat16(v.y - __bfloat162float(h1)));
    ls.z = __bfloat16_as_ushort(__float2bfloat16(v.z - __bfloat162float(h2)));
    ls.w = __bfloat16_as_ushort(__float2bfloat16(v.w - __bfloat162float(h3)));
    *(ushort4*)&g_xhi[i] = hs;
    *(ushort4*)&g_xlo[i] = ls;
}

__global__ __launch_bounds__(256)
void convw_kernel(const float* __restrict__ ww, const float* __restrict__ mw)
{
    const int tid = threadIdx.x;
    if (blockIdx.x == 0) {
        #pragma unroll
        for (int r = 0; r < 4; r++) g_flags[r * 256 + tid] = 0u;
        if (tid < NWIN) g_windone[tid] = 0u;
        if (tid == 0)   g_qhead = 0u;
    }
    int i = blockIdx.x * 256 + tid;
    int n = i >> 9;
    int k = i & 511;
    float w = (n < GW) ? ww[(size_t)k * GW + n] : mw[(size_t)k * L_ + (n - GW)];
    __nv_bfloat16 h = __float2bfloat16(w);
    g_whi[(size_t)n * 512 + k] = h;
    g_wlo[(size_t)n * 512 + k] = __float2bfloat16(w - __bfloat162float(h));
}

// ---------------------------------------------------------------------------
// Background worker: pulls 128x128 output tiles from the global queue
// (window-ordered) and computes PRE = X @ Wx + bias via bf16x3 HMMA.
// Runs as 256-thread groups: in-CTA halves of critical CTAs AND both halves
// of dedicated CTAs. Signals g_windone[w] (target WIN_TILES) per tile.
// ---------------------------------------------------------------------------
#define LSTM_BYTES 155648                       // 38912 floats (critical state)
#define TILE_B 18432                            // 128 rows * 144 B (72 bf16 pad)
#define BGBUF  (4 * TILE_B + 128)               // Ahi/Alo/Bhi/Blo + header
#define SMEM_TOTAL (LSTM_BYTES + BGBUF)         // 229504 B

#define CP16(dst, src) \
    asm volatile("cp.async.ca.shared.global [%0], [%1], 16;" :: "r"(dst), "l"(src))
#define BARC(id, n) asm volatile("bar.sync %0, %1;" :: "n"(id), "n"(n) : "memory")

__device__ __forceinline__ void bar_named(int id) {
    asm volatile("bar.sync %0, %1;" :: "r"(id), "n"(256) : "memory");
}

__device__ __forceinline__ void mma16816(float* d, const uint32_t* a, const uint32_t* b) {
    asm volatile(
        "mma.sync.aligned.m16n8k16.row.col.f32.bf16.bf16.f32 "
        "{%0,%1,%2,%3}, {%4,%5,%6,%7}, {%8,%9}, {%0,%1,%2,%3};"
        : "+f"(d[0]), "+f"(d[1]), "+f"(d[2]), "+f"(d[3])
        : "r"(a[0]), "r"(a[1]), "r"(a[2]), "r"(a[3]), "r"(b[0]), "r"(b[1]));
}

__device__ __forceinline__ float sigf(float x)     { return 1.f / (1.f + __expf(-x)); }
__device__ __forceinline__ float tanh_fast(float x){ return 2.f / (1.f + __expf(-2.f * x)) - 1.f; }

__device__ void bg_worker(char* bsm, int barid, int wtid,
                          const float* __restrict__ wb,
                          const float* __restrict__ mb)
{
    uint32_t bbase = smem_u32(bsm);
    unsigned* qslot = (unsigned*)(bsm + 4 * TILE_B);
    const int wid  = wtid >> 5;
    const int lane = wtid & 31;
    const int mh   = wid >> 2;
    const int nq   = wid & 3;
    const int l4   = lane >> 2;
    const int l2   = (lane & 3) * 2;
    const int prow = wtid >> 1;
    const int pk0  = (wtid & 1) * 4;

    for (;;) {
        if (wtid == 0) *qslot = atomicAdd(&g_qhead, 1u);
        bar_named(barid);
        unsigned id = *qslot;
        if (id >= NUNITS) break;
        const int w     = id >> 9;
        const int rem   = id & 511;
        const int slab  = rem >> 4;        // batch b
        const int ntile = rem & 15;
        const int m0 = slab * 2048 + w * 128;
        const int n0 = ntile * 128;

        float acc[4][4][4];
        #pragma unroll
        for (int mt = 0; mt < 4; mt++)
            #pragma unroll
            for (int ntf = 0; ntf < 4; ntf++)
                #pragma unroll
                for (int r = 0; r < 4; r++) acc[mt][ntf][r] = 0.f;

        for (int c = 0; c < 8; c++) {
            {
                uint32_t dbase = bbase + prow * 144;
                size_t ga = (size_t)(m0 + prow) * 512 + c * 64;
                size_t gb = (size_t)(n0 + prow) * 512 + c * 64;
                #pragma unroll
                for (int i = 0; i < 4; i++) {
                    int kb = pk0 + i;
                    CP16(dbase + kb * 16,              (const char*)&g_xhi[ga + kb * 8]);
                    CP16(dbase + kb * 16 + TILE_B,     (const char*)&g_xlo[ga + kb * 8]);
                    CP16(dbase + kb * 16 + 2 * TILE_B, (const char*)&g_whi[gb + kb * 8]);
                    CP16(dbase + kb * 16 + 3 * TILE_B, (const char*)&g_wlo[gb + kb * 8]);
                }
                asm volatile("cp.async.commit_group;" ::: "memory");
                asm volatile("cp.async.wait_group 0;" ::: "memory");
            }
            bar_named(barid);

            const __nv_bfloat16* sAhi = (const __nv_bfloat16*)bsm;
            const __nv_bfloat16* sAlo = (const __nv_bfloat16*)(bsm + TILE_B);
            const __nv_bfloat16* sBhi = (const __nv_bfloat16*)(bsm + 2 * TILE_B);
            const __nv_bfloat16* sBlo = (const __nv_bfloat16*)(bsm + 3 * TILE_B);
            #pragma unroll
            for (int p = 0; p < 3; p++) {
                const __nv_bfloat16* Ab = (p == 2) ? sAlo : sAhi;
                const __nv_bfloat16* Bb = (p == 1) ? sBlo : sBhi;
                #pragma unroll
                for (int ks = 0; ks < 4; ks++) {
                    const int C = ks * 16;
                    uint32_t bfr[4][2];
                    #pragma unroll
                    for (int ntf = 0; ntf < 4; ntf++) {
                        int nr = nq * 32 + ntf * 8 + l4;
                        bfr[ntf][0] = *(const uint32_t*)&Bb[nr * 72 + C + l2];
                        bfr[ntf][1] = *(const uint32_t*)&Bb[nr * 72 + C + 8 + l2];
                    }
                    #pragma unroll
                    for (int mt = 0; mt < 4; mt++) {
                        int r = mh * 64 + mt * 16 + l4;
                        uint32_t af[4];
                        af[0] = *(const uint32_t*)&Ab[r * 72 + C + l2];
                        af[1] = *(const uint32_t*)&Ab[(r + 8) * 72 + C + l2];
                        af[2] = *(const uint32_t*)&Ab[r * 72 + C + 8 + l2];
                        af[3] = *(const uint32_t*)&Ab[(r + 8) * 72 + C + 8 + l2];
                        #pragma unroll
                        for (int ntf = 0; ntf < 4; ntf++)
                            mma16816(acc[mt][ntf], af, bfr[ntf]);
                    }
                }
            }
            bar_named(barid);        // compute done before buffer refill
        }

        // epilogue: bias + store
        float bv[4][2];
        #pragma unroll
        for (int ntf = 0; ntf < 4; ntf++) {
            int lc = n0 + nq * 32 + ntf * 8 + l2;
            bv[ntf][0] = (lc < GW) ? wb[lc] : mb[lc - GW];
            bv[ntf][1] = (lc + 1 < GW) ? wb[lc + 1] : mb[lc + 1 - GW];
        }
        #pragma unroll
        for (int mt = 0; mt < 4; mt++) {
            int gr = m0 + mh * 64 + mt * 16 + l4;
            #pragma unroll
            for (int ntf = 0; ntf < 4; ntf++) {
                int lc = n0 + nq * 32 + ntf * 8 + l2;
                float2 o0 = make_float2(acc[mt][ntf][0] + bv[ntf][0],
                                        acc[mt][ntf][1] + bv[ntf][1]);
                float2 o1 = make_float2(acc[mt][ntf][2] + bv[ntf][0],
                                        acc[mt][ntf][3] + bv[ntf][1]);
                *(float2*)&g_pre[(size_t)gr * NG + lc]       = o0;
                *(float2*)&g_pre[(size_t)(gr + 8) * NG + lc] = o1;
            }
        }
        bar_named(barid);            // all stores hb-before release
        if (wtid == 0) red_rel_add(&g_windone[w], 1u);
    }
}

// ---------------------------------------------------------------------------
// Fused persistent kernel, GRID=152 CTAs x 512 threads:
//   blockIdx <  128: tid<256 background worker (queue), tid>=256 critical LSTM
//   blockIdx >= 128: both 256-thread halves are background workers
// Critical named barriers: 1 (epilogue,128), 2 (critical,256).
// Background barriers: 3 (group 0), 4 (group 1). No __syncthreads anywhere.
// ---------------------------------------------------------------------------
__global__ __launch_bounds__(512, 1)
void fused_kernel(const float* __restrict__ h0, const float* __restrict__ c0,
                  const float* __restrict__ ww, const float* __restrict__ wb,
                  const float* __restrict__ mw, const float* __restrict__ mb,
                  float* __restrict__ out)
{
    extern __shared__ float smem[];
    const int tid = threadIdx.x;

    if (blockIdx.x >= NCTA) {
        const int grp = tid >> 8;
        bg_worker((char*)smem + grp * BGBUF, 3 + grp, tid & 255, wb, mb);
        return;
    }
    if (tid < 256) {
        bg_worker((char*)smem + LSTM_BYTES, 3, tid, wb, mb);
        return;
    }

    // ===================== CRITICAL: recurrent LSTM ====================
    const int ct = tid - 256;
    float* sH   = smem;                 // sH[k*36 + b]
    float* sW   = smem + 512 * 36;      // sW[k*20 + j]
    float* sRed = sW + 512 * 20;        // sRed[par][ct*20 + v]

    const int L0 = blockIdx.x * 4;

    for (int it = ct; it < 16 * 512; it += 256) {
        int k = it >> 4;
        int j = it & 15;
        int g = j >> 2, jl = j & 3;
        float w;
        if (g < 3) w = ww[(size_t)(512 + k) * GW + g * 512 + L0 + jl];
        else       w = mw[(size_t)(512 + k) * L_ + L0 + jl];
        sW[k * 20 + j] = w;
    }

    const int s  = ct >> 5;
    const int u  = ct & 31;
    const int b0 = (u >> 2) * 4;
    const int j0 = (u & 3) * 4;
    const int kbase = s * 64;

    const int eb  = ct >> 2;
    const int ejl = ct & 3;
    float c_reg = 0.f;
    float pre_r[4];
    if (ct < 128) {
        c_reg = c0[eb * L_ + L0 + ejl];
        g_hbuf[(L0 + ejl) * 32 + eb] = h0[eb * L_ + L0 + ejl];
    }
    BARC(2, 256);
    if (ct == 0) st_rel(&g_flags[blockIdx.x * 8], 1u);

    if (ct < 128) {
        while (ld_acq(&g_windone[0]) < WIN_TILES) { }
        #pragma unroll
        for (int g = 0; g < 4; g++)
            pre_r[g] = g_pre[(size_t)eb * T_ * NG + g * 512 + L0 + ejl];
    }

    float* hid  = out;
    float* cell = out + (size_t)B_ * T_ * L_;

    const unsigned* myflag = &g_flags[(s * 16 + (u & 15)) * 8];

    int par = 0;
    for (int t = 0; t < T_; t++) {
        {
            const unsigned tgt = (unsigned)(t + 1);
            for (;;) {
                unsigned v = ld_acq(myflag);
                if (__all_sync(0xffffffffu, v >= tgt)) break;
            }
            const float* buf = g_hbuf + (size_t)(t & 1) * (L_ * 32);
            #pragma unroll
            for (int qq = 0; qq < 16; qq++) {
                int f = qq * 32 + u;
                int krow = kbase + (f >> 3);
                int c4 = (f & 7) * 4;
                float4 v4 = *(const float4*)&buf[krow * 32 + c4];
                *(float4*)&sH[krow * 36 + c4] = v4;
            }
            __syncwarp();
        }

        float acc[4][4];
        #pragma unroll
        for (int i = 0; i < 4; i++)
            #pragma unroll
            for (int j = 0; j < 4; j++) acc[i][j] = 0.f;

        const float* hp = sH + kbase * 36 + b0;
        const float* wp = sW + kbase * 20 + j0;
        #pragma unroll 8
        for (int kk = 0; kk < 64; kk++) {
            float4 hv = *(const float4*)hp;
            float4 wv = *(const float4*)wp;
            acc[0][0] += hv.x * wv.x; acc[0][1] += hv.x * wv.y;
            acc[0][2] += hv.x * wv.z; acc[0][3] += hv.x * wv.w;
            acc[1][0] += hv.y * wv.x; acc[1][1] += hv.y * wv.y;
            acc[1][2] += hv.y * wv.z; acc[1][3] += hv.y * wv.w;
            acc[2][0] += hv.z * wv.x; acc[2][1] += hv.z * wv.y;
            acc[2][2] += hv.z * wv.z; acc[2][3] += hv.z * wv.w;
            acc[3][0] += hv.w * wv.x; acc[3][1] += hv.w * wv.y;
            acc[3][2] += hv.w * wv.z; acc[3][3] += hv.w * wv.w;
            hp += 36; wp += 20;
        }
        float* red = sRed + par * (256 * 20);
        #pragma unroll
        for (int i = 0; i < 4; i++) {
            float4 v = make_float4(acc[i][0], acc[i][1], acc[i][2], acc[i][3]);
            *(float4*)&red[ct * 20 + i * 4] = v;
        }
        BARC(2, 256);

        if (ct < 128) {
            float z[4];
            #pragma unroll
            for (int g = 0; g < 4; g++) {
                float v = 0.f;
                #pragma unroll
                for (int ss = 0; ss < 8; ss++)
                    v += red[(ss * 32 + (eb >> 2) * 4 + g) * 20 + (eb & 3) * 4 + ejl];
                z[g] = v + pre_r[g];
            }
            float ig = sigf(z[0]);
            float fg = sigf(z[1]);
            float og = sigf(z[2]);
            float mg = tanh_fast(z[3]);
            c_reg = fg * c_reg + ig * mg;
            float hn = og * tanh_fast(c_reg);
            size_t off = ((size_t)eb * T_ + t) * L_ + L0 + ejl;
            if (t + 1 < T_) {
                // publish FIRST, release EARLY, then do deferred work
                float* nb = g_hbuf + (size_t)((t + 1) & 1) * (L_ * 32);
                nb[(L0 + ejl) * 32 + eb] = hn;
                BARC(1, 128);
                if (ct == 0)
                    st_rel(&g_flags[blockIdx.x * 8], (unsigned)(t + 2));
                hid[off]  = hn;
                cell[off] = c_reg;
                if (((t + 1) & 127) == 0) {
                    const unsigned* wd = &g_windone[(t + 1) >> 7];
                    while (ld_acq(wd) < WIN_TILES) { }
                }
                #pragma unroll
                for (int g = 0; g < 4; g++)
                    pre_r[g] = g_pre[((size_t)eb * T_ + (t + 1)) * NG + g * 512 + L0 + ejl];
            } else {
                hid[off]  = hn;
                cell[off] = c_reg;
            }
        }
        par ^= 1;
    }
}

// ---------------------------------------------------------------------------
extern "C" void kernel_launch(void* const* d_in, const int* in_sizes, int n_in,
                              void* d_out, int out_size)
{
    const float* x  = (const float*)d_in[0];
    const float* h0 = (const float*)d_in[1];
    const float* c0 = (const float*)d_in[2];
    const float* ww = (const float*)d_in[3];
    const float* wb = (const float*)d_in[4];
    const float* mw = (const float*)d_in[5];
    const float* mb = (const float*)d_in[6];
    float* out = (float*)d_out;

    cudaFuncSetAttribute(fused_kernel,
                         cudaFuncAttributeMaxDynamicSharedMemorySize, SMEM_TOTAL);

    convx_kernel<<<32768, 256>>>(x);
    convw_kernel<<<4096, 256>>>(ww, mw);
    fused_kernel<<<GRID, 512, SMEM_TOTAL>>>(h0, c0, ww, wb, mw, mb, out);
}

// round 16
// speedup vs baseline: 1.1796x; 1.0073x over previous
#include <cuda_runtime.h>
#include <cuda_fp16.h>
#include <cstdint>
#include <cstddef>

#define B_  32
#define T_  2048
#define D_  512
#define L_  512
#define NG  2048          // 3L gate cols + L candidate cols
#define GW  1536          // w_w column count

// Scratch: precomputed x-part of preactivations (+bias), fp16 split copies.
__device__ float g_pre[(size_t)B_ * T_ * NG];
__device__ __half g_xhi[(size_t)B_ * T_ * D_];
__device__ __half g_xlo[(size_t)B_ * T_ * D_];
__device__ __half g_whi[(size_t)NG * D_];          // W^T [n][k], fp16(w)

#define NCTA 128          // critical CTAs (l-split)
#define NBG  24           // dedicated background CTAs
#define GRID (NCTA + NBG)
#define NWIN 16
#define NUNITS 8192       // 512 m-tiles x 16 n-tiles
#define WIN_TILES 512u    // tiles per 128-step window

__device__ unsigned int g_flags[NCTA * 8];     // h-publication flags
__device__ unsigned int g_windone[NWIN];       // per-window tile counters
__device__ unsigned int g_qhead;               // tile queue head
__device__ float g_hbuf[2 * L_ * B_];

__device__ __forceinline__ unsigned ld_acq(const unsigned* p) {
    unsigned v;
    asm volatile("ld.acquire.gpu.global.u32 %0, [%1];" : "=r"(v) : "l"(p));
    return v;
}
__device__ __forceinline__ void st_rel(unsigned* p, unsigned v) {
    asm volatile("st.release.gpu.global.u32 [%0], %1;" :: "l"(p), "r"(v));
}
__device__ __forceinline__ void red_rel_add(unsigned* p, unsigned v) {
    asm volatile("red.release.gpu.global.add.u32 [%0], %1;" :: "l"(p), "r"(v));
}
__device__ __forceinline__ uint32_t smem_u32(const void* p) {
    uint32_t a;
    asm("{ .reg .u64 t; cvta.to.shared.u64 t, %1; cvt.u32.u64 %0, t; }" : "=r"(a) : "l"(p));
    return a;
}

// ---------------------------------------------------------------------------
// Prep kernels: split fp32 -> fp16 hi/lo (x), fp16 (w); reset state (convw)
// ---------------------------------------------------------------------------
__global__ __launch_bounds__(256)
void convx_kernel(const float* __restrict__ x)
{
    size_t i = ((size_t)blockIdx.x * 256 + threadIdx.x) * 4;
    float4 v = *(const float4*)(x + i);
    __half h0 = __float2half_rn(v.x);
    __half h1 = __float2half_rn(v.y);
    __half h2 = __float2half_rn(v.z);
    __half h3 = __float2half_rn(v.w);
    ushort4 hs, ls;
    hs.x = __half_as_ushort(h0); hs.y = __half_as_ushort(h1);
    hs.z = __half_as_ushort(h2); hs.w = __half_as_ushort(h3);
    ls.x = __half_as_ushort(__float2half_rn(v.x - __half2float(h0)));
    ls.y = __half_as_ushort(__float2half_rn(v.y - __half2float(h1)));
    ls.z = __half_as_ushort(__float2half_rn(v.z - __half2float(h2)));
    ls.w = __half_as_ushort(__float2half_rn(v.w - __half2float(h3)));
    *(ushort4*)&g_xhi[i] = hs;
    *(ushort4*)&g_xlo[i] = ls;
}

__global__ __launch_bounds__(256)
void convw_kernel(const float* __restrict__ ww, const float* __restrict__ mw)
{
    const int tid = threadIdx.x;
    if (blockIdx.x == 0) {
        #pragma unroll
        for (int r = 0; r < 4; r++) g_flags[r * 256 + tid] = 0u;
        if (tid < NWIN) g_windone[tid] = 0u;
        if (tid == 0)   g_qhead = 0u;
    }
    int i = blockIdx.x * 256 + tid;
    int n = i >> 9;
    int k = i & 511;
    float w = (n < GW) ? ww[(size_t)k * GW + n] : mw[(size_t)k * L_ + (n - GW)];
    g_whi[(size_t)n * 512 + k] = __float2half_rn(w);
}

// ---------------------------------------------------------------------------
// Background worker: pulls 128x128 output tiles from the global queue and
// computes PRE = X @ Wx + bias via 2-pass fp16 HMMA:
//   pass 0: x_hi * w_f16,  pass 1: x_lo * w_f16   (B fragments hoisted).
// ---------------------------------------------------------------------------
#define LSTM_BYTES 155648                       // 38912 floats (critical state)
#define TILE_B 18432                            // 128 rows * 144 B (72 f16 pad)
#define BGBUF  (3 * TILE_B + 128)               // Ahi/Alo/Bhi + header
#define SMEM_TOTAL (LSTM_BYTES + BGBUF)

#define CP16(dst, src) \
    asm volatile("cp.async.ca.shared.global [%0], [%1], 16;" :: "r"(dst), "l"(src))
#define BARC(id, n) asm volatile("bar.sync %0, %1;" :: "n"(id), "n"(n) : "memory")

__device__ __forceinline__ void bar_named(int id) {
    asm volatile("bar.sync %0, %1;" :: "r"(id), "n"(256) : "memory");
}

__device__ __forceinline__ void mma16816h(float* d, const uint32_t* a, const uint32_t* b) {
    asm volatile(
        "mma.sync.aligned.m16n8k16.row.col.f32.f16.f16.f32 "
        "{%0,%1,%2,%3}, {%4,%5,%6,%7}, {%8,%9}, {%0,%1,%2,%3};"
        : "+f"(d[0]), "+f"(d[1]), "+f"(d[2]), "+f"(d[3])
        : "r"(a[0]), "r"(a[1]), "r"(a[2]), "r"(a[3]), "r"(b[0]), "r"(b[1]));
}

__device__ __forceinline__ float sigf(float x)     { return 1.f / (1.f + __expf(-x)); }
__device__ __forceinline__ float tanh_fast(float x){ return 2.f / (1.f + __expf(-2.f * x)) - 1.f; }

__device__ void bg_worker(char* bsm, int barid, int wtid,
                          const float* __restrict__ wb,
                          const float* __restrict__ mb)
{
    uint32_t bbase = smem_u32(bsm);
    unsigned* qslot = (unsigned*)(bsm + 3 * TILE_B);
    const int wid  = wtid >> 5;
    const int lane = wtid & 31;
    const int mh   = wid >> 2;
    const int nq   = wid & 3;
    const int l4   = lane >> 2;
    const int l2   = (lane & 3) * 2;
    const int prow = wtid >> 1;
    const int pk0  = (wtid & 1) * 4;

    for (;;) {
        if (wtid == 0) *qslot = atomicAdd(&g_qhead, 1u);
        bar_named(barid);
        unsigned id = *qslot;
        if (id >= NUNITS) break;
        const int w     = id >> 9;
        const int rem   = id & 511;
        const int slab  = rem >> 4;        // batch b
        const int ntile = rem & 15;
        const int m0 = slab * 2048 + w * 128;
        const int n0 = ntile * 128;

        float acc[4][4][4];
        #pragma unroll
        for (int mt = 0; mt < 4; mt++)
            #pragma unroll
            for (int ntf = 0; ntf < 4; ntf++)
                #pragma unroll
                for (int r = 0; r < 4; r++) acc[mt][ntf][r] = 0.f;

        for (int c = 0; c < 8; c++) {
            {
                uint32_t dbase = bbase + prow * 144;
                size_t ga = (size_t)(m0 + prow) * 512 + c * 64;
                size_t gb = (size_t)(n0 + prow) * 512 + c * 64;
                #pragma unroll
                for (int i = 0; i < 4; i++) {
                    int kb = pk0 + i;
                    CP16(dbase + kb * 16,              (const char*)&g_xhi[ga + kb * 8]);
                    CP16(dbase + kb * 16 + TILE_B,     (const char*)&g_xlo[ga + kb * 8]);
                    CP16(dbase + kb * 16 + 2 * TILE_B, (const char*)&g_whi[gb + kb * 8]);
                }
                asm volatile("cp.async.commit_group;" ::: "memory");
                asm volatile("cp.async.wait_group 0;" ::: "memory");
            }
            bar_named(barid);

            const __half* sAhi = (const __half*)bsm;
            const __half* sAlo = (const __half*)(bsm + TILE_B);
            const __half* sBhi = (const __half*)(bsm + 2 * TILE_B);
            #pragma unroll
            for (int ks = 0; ks < 4; ks++) {
                const int C = ks * 16;
                uint32_t bfr[4][2];
                #pragma unroll
                for (int ntf = 0; ntf < 4; ntf++) {
                    int nr = nq * 32 + ntf * 8 + l4;
                    bfr[ntf][0] = *(const uint32_t*)&sBhi[nr * 72 + C + l2];
                    bfr[ntf][1] = *(const uint32_t*)&sBhi[nr * 72 + C + 8 + l2];
                }
                #pragma unroll
                for (int p = 0; p < 2; p++) {
                    const __half* Ab = (p == 1) ? sAlo : sAhi;
                    #pragma unroll
                    for (int mt = 0; mt < 4; mt++) {
                        int r = mh * 64 + mt * 16 + l4;
                        uint32_t af[4];
                        af[0] = *(const uint32_t*)&Ab[r * 72 + C + l2];
                        af[1] = *(const uint32_t*)&Ab[(r + 8) * 72 + C + l2];
                        af[2] = *(const uint32_t*)&Ab[r * 72 + C + 8 + l2];
                        af[3] = *(const uint32_t*)&Ab[(r + 8) * 72 + C + 8 + l2];
                        #pragma unroll
                        for (int ntf = 0; ntf < 4; ntf++)
                            mma16816h(acc[mt][ntf], af, bfr[ntf]);
                    }
                }
            }
            bar_named(barid);        // compute done before buffer refill
        }

        // epilogue: bias + store
        float bv[4][2];
        #pragma unroll
        for (int ntf = 0; ntf < 4; ntf++) {
            int lc = n0 + nq * 32 + ntf * 8 + l2;
            bv[ntf][0] = (lc < GW) ? wb[lc] : mb[lc - GW];
            bv[ntf][1] = (lc + 1 < GW) ? wb[lc + 1] : mb[lc + 1 - GW];
        }
        #pragma unroll
        for (int mt = 0; mt < 4; mt++) {
            int gr = m0 + mh * 64 + mt * 16 + l4;
            #pragma unroll
            for (int ntf = 0; ntf < 4; ntf++) {
                int lc = n0 + nq * 32 + ntf * 8 + l2;
                float2 o0 = make_float2(acc[mt][ntf][0] + bv[ntf][0],
                                        acc[mt][ntf][1] + bv[ntf][1]);
                float2 o1 = make_float2(acc[mt][ntf][2] + bv[ntf][0],
                                        acc[mt][ntf][3] + bv[ntf][1]);
                *(float2*)&g_pre[(size_t)gr * NG + lc]       = o0;
                *(float2*)&g_pre[(size_t)(gr + 8) * NG + lc] = o1;
            }
        }
        bar_named(barid);            // all stores hb-before release
        if (wtid == 0) red_rel_add(&g_windone[w], 1u);
    }
}

// ---------------------------------------------------------------------------
// Fused persistent kernel, GRID=152 CTAs x 512 threads:
//   blockIdx <  128: tid<256 background worker (queue), tid>=256 critical LSTM
//   blockIdx >= 128: both 256-thread halves are background workers
// Critical named barriers: 1 (epilogue,128), 2 (critical,256).
// Background barriers: 3 (group 0), 4 (group 1). No __syncthreads anywhere.
// ---------------------------------------------------------------------------
__global__ __launch_bounds__(512, 1)
void fused_kernel(const float* __restrict__ h0, const float* __restrict__ c0,
                  const float* __restrict__ ww, const float* __restrict__ wb,
                  const float* __restrict__ mw, const float* __restrict__ mb,
                  float* __restrict__ out)
{
    extern __shared__ float smem[];
    const int tid = threadIdx.x;

    if (blockIdx.x >= NCTA) {
        const int grp = tid >> 8;
        bg_worker((char*)smem + grp * BGBUF, 3 + grp, tid & 255, wb, mb);
        return;
    }
    if (tid < 256) {
        bg_worker((char*)smem + LSTM_BYTES, 3, tid, wb, mb);
        return;
    }

    // ===================== CRITICAL: recurrent LSTM ====================
    const int ct = tid - 256;
    float* sH   = smem;                 // sH[k*36 + b]
    float* sW   = smem + 512 * 36;      // sW[k*20 + j]
    float* sRed = sW + 512 * 20;        // sRed[par][ct*20 + v]

    const int L0 = blockIdx.x * 4;

    for (int it = ct; it < 16 * 512; it += 256) {
        int k = it >> 4;
        int j = it & 15;
        int g = j >> 2, jl = j & 3;
        float w;
        if (g < 3) w = ww[(size_t)(512 + k) * GW + g * 512 + L0 + jl];
        else       w = mw[(size_t)(512 + k) * L_ + L0 + jl];
        sW[k * 20 + j] = w;
    }

    const int s  = ct >> 5;
    const int u  = ct & 31;
    const int b0 = (u >> 2) * 4;
    const int j0 = (u & 3) * 4;
    const int kbase = s * 64;

    const int eb  = ct >> 2;
    const int ejl = ct & 3;
    float c_reg = 0.f;
    float pre_r[4];
    if (ct < 128) {
        c_reg = c0[eb * L_ + L0 + ejl];
        g_hbuf[(L0 + ejl) * 32 + eb] = h0[eb * L_ + L0 + ejl];
    }
    BARC(2, 256);
    if (ct == 0) st_rel(&g_flags[blockIdx.x * 8], 1u);

    if (ct < 128) {
        while (ld_acq(&g_windone[0]) < WIN_TILES) { }
        #pragma unroll
        for (int g = 0; g < 4; g++)
            pre_r[g] = g_pre[(size_t)eb * T_ * NG + g * 512 + L0 + ejl];
    }

    float* hid  = out;
    float* cell = out + (size_t)B_ * T_ * L_;

    const unsigned* myflag = &g_flags[(s * 16 + (u & 15)) * 8];

    int par = 0;
    for (int t = 0; t < T_; t++) {
        {
            const unsigned tgt = (unsigned)(t + 1);
            for (;;) {
                unsigned v = ld_acq(myflag);
                if (__all_sync(0xffffffffu, v >= tgt)) break;
            }
            const float* buf = g_hbuf + (size_t)(t & 1) * (L_ * 32);
            #pragma unroll
            for (int qq = 0; qq < 16; qq++) {
                int f = qq * 32 + u;
                int krow = kbase + (f >> 3);
                int c4 = (f & 7) * 4;
                float4 v4 = *(const float4*)&buf[krow * 32 + c4];
                *(float4*)&sH[krow * 36 + c4] = v4;
            }
            __syncwarp();
        }

        float acc[4][4];
        #pragma unroll
        for (int i = 0; i < 4; i++)
            #pragma unroll
            for (int j = 0; j < 4; j++) acc[i][j] = 0.f;

        const float* hp = sH + kbase * 36 + b0;
        const float* wp = sW + kbase * 20 + j0;
        #pragma unroll 8
        for (int kk = 0; kk < 64; kk++) {
            float4 hv = *(const float4*)hp;
            float4 wv = *(const float4*)wp;
            acc[0][0] += hv.x * wv.x; acc[0][1] += hv.x * wv.y;
            acc[0][2] += hv.x * wv.z; acc[0][3] += hv.x * wv.w;
            acc[1][0] += hv.y * wv.x; acc[1][1] += hv.y * wv.y;
            acc[1][2] += hv.y * wv.z; acc[1][3] += hv.y * wv.w;
            acc[2][0] += hv.z * wv.x; acc[2][1] += hv.z * wv.y;
            acc[2][2] += hv.z * wv.z; acc[2][3] += hv.z * wv.w;
            acc[3][0] += hv.w * wv.x; acc[3][1] += hv.w * wv.y;
            acc[3][2] += hv.w * wv.z; acc[3][3] += hv.w * wv.w;
            hp += 36; wp += 20;
        }
        float* red = sRed + par * (256 * 20);
        #pragma unroll
        for (int i = 0; i < 4; i++) {
            float4 v = make_float4(acc[i][0], acc[i][1], acc[i][2], acc[i][3]);
            *(float4*)&red[ct * 20 + i * 4] = v;
        }
        BARC(2, 256);

        if (ct < 128) {
            float z[4];
            #pragma unroll
            for (int g = 0; g < 4; g++) {
                float v = 0.f;
                #pragma unroll
                for (int ss = 0; ss < 8; ss++)
                    v += red[(ss * 32 + (eb >> 2) * 4 + g) * 20 + (eb & 3) * 4 + ejl];
                z[g] = v + pre_r[g];
            }
            float ig = sigf(z[0]);
            float fg = sigf(z[1]);
            float og = sigf(z[2]);
            float mg = tanh_fast(z[3]);
            c_reg = fg * c_reg + ig * mg;
            float hn = og * tanh_fast(c_reg);
            size_t off = ((size_t)eb * T_ + t) * L_ + L0 + ejl;
            if (t + 1 < T_) {
                // publish FIRST, release EARLY, then do deferred work
                float* nb = g_hbuf + (size_t)((t + 1) & 1) * (L_ * 32);
                nb[(L0 + ejl) * 32 + eb] = hn;
                BARC(1, 128);
                if (ct == 0)
                    st_rel(&g_flags[blockIdx.x * 8], (unsigned)(t + 2));
                hid[off]  = hn;
                cell[off] = c_reg;
                if (((t + 1) & 127) == 0) {
                    const unsigned* wd = &g_windone[(t + 1) >> 7];
                    while (ld_acq(wd) < WIN_TILES) { }
                }
                #pragma unroll
                for (int g = 0; g < 4; g++)
                    pre_r[g] = g_pre[((size_t)eb * T_ + (t + 1)) * NG + g * 512 + L0 + ejl];
            } else {
                hid[off]  = hn;
                cell[off] = c_reg;
            }
        }
        par ^= 1;
    }
}

// ---------------------------------------------------------------------------
extern "C" void kernel_launch(void* const* d_in, const int* in_sizes, int n_in,
                              void* d_out, int out_size)
{
    const float* x  = (const float*)d_in[0];
    const float* h0 = (const float*)d_in[1];
    const float* c0 = (const float*)d_in[2];
    const float* ww = (const float*)d_in[3];
    const float* wb = (const float*)d_in[4];
    const float* mw = (const float*)d_in[5];
    const float* mb = (const float*)d_in[6];
    float* out = (float*)d_out;

    cudaFuncSetAttribute(fused_kernel,
                         cudaFuncAttributeMaxDynamicSharedMemorySize, SMEM_TOTAL);

    convx_kernel<<<32768, 256>>>(x);
    convw_kernel<<<4096, 256>>>(ww, mw);
    fused_kernel<<<GRID, 512, SMEM_TOTAL>>>(h0, c0, ww, wb, mw, mb, out);
}

// round 17
// speedup vs baseline: 1.5689x; 1.3301x over previous
#include <cuda_runtime.h>
#include <cuda_fp16.h>
#include <cstdint>
#include <cstddef>

#define B_  32
#define T_  2048
#define D_  512
#define L_  512
#define NG  2048          // 3L gate cols + L candidate cols
#define GW  1536          // w_w column count

// Scratch: precomputed x-part of preactivations (+bias), fp16 split copies.
__device__ float g_pre[(size_t)B_ * T_ * NG];
__device__ __half g_xhi[(size_t)B_ * T_ * D_];
__device__ __half g_xlo[(size_t)B_ * T_ * D_];
__device__ __half g_whi[(size_t)NG * D_];          // W_x^T [n][k], fp16(w)

#define NCTA 128          // critical CTAs (l-split)
#define NBG  24           // dedicated background CTAs
#define GRID (NCTA + NBG)
#define NWIN 16
#define NUNITS 8192       // 512 m-tiles x 16 n-tiles
#define WIN_TILES 512u    // tiles per 128-step window

__device__ unsigned int g_flags[NCTA * 8];     // h-publication flags
__device__ unsigned int g_windone[NWIN];       // per-window tile counters
__device__ unsigned int g_qhead;               // tile queue head
// h broadcast, packed {fp16 hi, fp16 lo} per (l, b): g_hbuf[par][l*32+b]
__device__ unsigned int g_hbuf[2 * L_ * B_];

__device__ __forceinline__ unsigned ld_acq(const unsigned* p) {
    unsigned v;
    asm volatile("ld.acquire.gpu.global.u32 %0, [%1];" : "=r"(v) : "l"(p));
    return v;
}
__device__ __forceinline__ void st_rel(unsigned* p, unsigned v) {
    asm volatile("st.release.gpu.global.u32 [%0], %1;" :: "l"(p), "r"(v));
}
__device__ __forceinline__ void red_rel_add(unsigned* p, unsigned v) {
    asm volatile("red.release.gpu.global.add.u32 [%0], %1;" :: "l"(p), "r"(v));
}
__device__ __forceinline__ uint32_t smem_u32(const void* p) {
    uint32_t a;
    asm("{ .reg .u64 t; cvta.to.shared.u64 t, %1; cvt.u32.u64 %0, t; }" : "=r"(a) : "l"(p));
    return a;
}
__device__ __forceinline__ unsigned pack_hilo(float v) {
    __half hh = __float2half_rn(v);
    __half hl = __float2half_rn(v - __half2float(hh));
    return (unsigned)__half_as_ushort(hh) | ((unsigned)__half_as_ushort(hl) << 16);
}

// ---------------------------------------------------------------------------
// Prep kernel (single launch): x -> fp16 hi/lo; blocks<4096 also convert W_x;
// block 0 resets flags/window counters/queue head.
// ---------------------------------------------------------------------------
__global__ __launch_bounds__(256)
void conv_kernel(const float* __restrict__ x,
                 const float* __restrict__ ww, const float* __restrict__ mw)
{
    const int tid = threadIdx.x;
    if (blockIdx.x == 0) {
        #pragma unroll
        for (int r = 0; r < 4; r++) g_flags[r * 256 + tid] = 0u;
        if (tid < NWIN) g_windone[tid] = 0u;
        if (tid == 0)   g_qhead = 0u;
    }
    size_t i = ((size_t)blockIdx.x * 256 + tid) * 4;
    float4 v = *(const float4*)(x + i);
    __half h0 = __float2half_rn(v.x);
    __half h1 = __float2half_rn(v.y);
    __half h2 = __float2half_rn(v.z);
    __half h3 = __float2half_rn(v.w);
    ushort4 hs, ls;
    hs.x = __half_as_ushort(h0); hs.y = __half_as_ushort(h1);
    hs.z = __half_as_ushort(h2); hs.w = __half_as_ushort(h3);
    ls.x = __half_as_ushort(__float2half_rn(v.x - __half2float(h0)));
    ls.y = __half_as_ushort(__float2half_rn(v.y - __half2float(h1)));
    ls.z = __half_as_ushort(__float2half_rn(v.z - __half2float(h2)));
    ls.w = __half_as_ushort(__float2half_rn(v.w - __half2float(h3)));
    *(ushort4*)&g_xhi[i] = hs;
    *(ushort4*)&g_xlo[i] = ls;

    if (blockIdx.x < 4096) {
        int e = blockIdx.x * 256 + tid;        // 0 .. NG*512-1
        int n = e >> 9;
        int k = e & 511;
        float w = (n < GW) ? ww[(size_t)k * GW + n] : mw[(size_t)k * L_ + (n - GW)];
        g_whi[(size_t)n * 512 + k] = __float2half_rn(w);
    }
}

// ---------------------------------------------------------------------------
// Background worker: 2-pass fp16 HMMA for PRE = X @ Wx + bias (queue-driven).
// ---------------------------------------------------------------------------
// critical smem: sH32 u32[512][40] + sW32 u32[16][516] + sRed f32[2][8][640]
#define SH32_U32 (512 * 40)
#define SW32_U32 (16 * 516)
#define RED_F    (2 * 8 * 640)
#define LSTM_BYTES ((SH32_U32 + SW32_U32 + RED_F) * 4)      // 155904
#define TILE_B 18432                            // 128 rows * 144 B (72 f16 pad)
#define BGBUF  (3 * TILE_B + 128)               // Ahi/Alo/Bhi + header
#define SMEM_TOTAL (LSTM_BYTES + BGBUF)

#define CP16(dst, src) \
    asm volatile("cp.async.ca.shared.global [%0], [%1], 16;" :: "r"(dst), "l"(src))
#define BARC(id, n) asm volatile("bar.sync %0, %1;" :: "n"(id), "n"(n) : "memory")

__device__ __forceinline__ void bar_named(int id) {
    asm volatile("bar.sync %0, %1;" :: "r"(id), "n"(256) : "memory");
}

__device__ __forceinline__ void mma16816h(float* d, const uint32_t* a, const uint32_t* b) {
    asm volatile(
        "mma.sync.aligned.m16n8k16.row.col.f32.f16.f16.f32 "
        "{%0,%1,%2,%3}, {%4,%5,%6,%7}, {%8,%9}, {%0,%1,%2,%3};"
        : "+f"(d[0]), "+f"(d[1]), "+f"(d[2]), "+f"(d[3])
        : "r"(a[0]), "r"(a[1]), "r"(a[2]), "r"(a[3]), "r"(b[0]), "r"(b[1]));
}

__device__ __forceinline__ float sigf(float x)     { return 1.f / (1.f + __expf(-x)); }
__device__ __forceinline__ float tanh_fast(float x){ return 2.f / (1.f + __expf(-2.f * x)) - 1.f; }

__device__ void bg_worker(char* bsm, int barid, int wtid,
                          const float* __restrict__ wb,
                          const float* __restrict__ mb)
{
    uint32_t bbase = smem_u32(bsm);
    unsigned* qslot = (unsigned*)(bsm + 3 * TILE_B);
    const int wid  = wtid >> 5;
    const int lane = wtid & 31;
    const int mh   = wid >> 2;
    const int nq   = wid & 3;
    const int l4   = lane >> 2;
    const int l2   = (lane & 3) * 2;
    const int prow = wtid >> 1;
    const int pk0  = (wtid & 1) * 4;

    for (;;) {
        if (wtid == 0) *qslot = atomicAdd(&g_qhead, 1u);
        bar_named(barid);
        unsigned id = *qslot;
        if (id >= NUNITS) break;
        const int w     = id >> 9;
        const int rem   = id & 511;
        const int slab  = rem >> 4;        // batch b
        const int ntile = rem & 15;
        const int m0 = slab * 2048 + w * 128;
        const int n0 = ntile * 128;

        float acc[4][4][4];
        #pragma unroll
        for (int mt = 0; mt < 4; mt++)
            #pragma unroll
            for (int ntf = 0; ntf < 4; ntf++)
                #pragma unroll
                for (int r = 0; r < 4; r++) acc[mt][ntf][r] = 0.f;

        for (int c = 0; c < 8; c++) {
            {
                uint32_t dbase = bbase + prow * 144;
                size_t ga = (size_t)(m0 + prow) * 512 + c * 64;
                size_t gb = (size_t)(n0 + prow) * 512 + c * 64;
                #pragma unroll
                for (int i = 0; i < 4; i++) {
                    int kb = pk0 + i;
                    CP16(dbase + kb * 16,              (const char*)&g_xhi[ga + kb * 8]);
                    CP16(dbase + kb * 16 + TILE_B,     (const char*)&g_xlo[ga + kb * 8]);
                    CP16(dbase + kb * 16 + 2 * TILE_B, (const char*)&g_whi[gb + kb * 8]);
                }
                asm volatile("cp.async.commit_group;" ::: "memory");
                asm volatile("cp.async.wait_group 0;" ::: "memory");
            }
            bar_named(barid);

            const __half* sAhi = (const __half*)bsm;
            const __half* sAlo = (const __half*)(bsm + TILE_B);
            const __half* sBhi = (const __half*)(bsm + 2 * TILE_B);
            #pragma unroll
            for (int ks = 0; ks < 4; ks++) {
                const int C = ks * 16;
                uint32_t bfr[4][2];
                #pragma unroll
                for (int ntf = 0; ntf < 4; ntf++) {
                    int nr = nq * 32 + ntf * 8 + l4;
                    bfr[ntf][0] = *(const uint32_t*)&sBhi[nr * 72 + C + l2];
                    bfr[ntf][1] = *(const uint32_t*)&sBhi[nr * 72 + C + 8 + l2];
                }
                #pragma unroll
                for (int p = 0; p < 2; p++) {
                    const __half* Ab = (p == 1) ? sAlo : sAhi;
                    #pragma unroll
                    for (int mt = 0; mt < 4; mt++) {
                        int r = mh * 64 + mt * 16 + l4;
                        uint32_t af[4];
                        af[0] = *(const uint32_t*)&Ab[r * 72 + C + l2];
                        af[1] = *(const uint32_t*)&Ab[(r + 8) * 72 + C + l2];
                        af[2] = *(const uint32_t*)&Ab[r * 72 + C + 8 + l2];
                        af[3] = *(const uint32_t*)&Ab[(r + 8) * 72 + C + 8 + l2];
                        #pragma unroll
                        for (int ntf = 0; ntf < 4; ntf++)
                            mma16816h(acc[mt][ntf], af, bfr[ntf]);
                    }
                }
            }
            bar_named(barid);        // compute done before buffer refill
        }

        // epilogue: bias + store
        float bv[4][2];
        #pragma unroll
        for (int ntf = 0; ntf < 4; ntf++) {
            int lc = n0 + nq * 32 + ntf * 8 + l2;
            bv[ntf][0] = (lc < GW) ? wb[lc] : mb[lc - GW];
            bv[ntf][1] = (lc + 1 < GW) ? wb[lc + 1] : mb[lc + 1 - GW];
        }
        #pragma unroll
        for (int mt = 0; mt < 4; mt++) {
            int gr = m0 + mh * 64 + mt * 16 + l4;
            #pragma unroll
            for (int ntf = 0; ntf < 4; ntf++) {
                int lc = n0 + nq * 32 + ntf * 8 + l2;
                float2 o0 = make_float2(acc[mt][ntf][0] + bv[ntf][0],
                                        acc[mt][ntf][1] + bv[ntf][1]);
                float2 o1 = make_float2(acc[mt][ntf][2] + bv[ntf][0],
                                        acc[mt][ntf][3] + bv[ntf][1]);
                *(float2*)&g_pre[(size_t)gr * NG + lc]       = o0;
                *(float2*)&g_pre[(size_t)(gr + 8) * NG + lc] = o1;
            }
        }
        bar_named(barid);            // all stores hb-before release
        if (wtid == 0) red_rel_add(&g_windone[w], 1u);
    }
}

// ---------------------------------------------------------------------------
// Fused persistent kernel, GRID=152 CTAs x 512 threads.
//   Critical half: recurrent LSTM with HMMA h-GEMM:
//     h published as packed {fp16 hi, fp16 lo} u32 -> K'=1024 single sweep
//     against pair-duplicated fp16 Wh; fp32 accumulate; K-split 8 warps +
//     sRed reduce + fp32 gate epilogue (c stays fp32 in registers).
// ---------------------------------------------------------------------------
__global__ __launch_bounds__(512, 1)
void fused_kernel(const float* __restrict__ h0, const float* __restrict__ c0,
                  const float* __restrict__ ww, const float* __restrict__ wb,
                  const float* __restrict__ mw, const float* __restrict__ mb,
                  float* __restrict__ out)
{
    extern __shared__ float smem[];
    const int tid = threadIdx.x;

    if (blockIdx.x >= NCTA) {
        const int grp = tid >> 8;
        bg_worker((char*)smem + grp * BGBUF, 3 + grp, tid & 255, wb, mb);
        return;
    }
    if (tid < 256) {
        bg_worker((char*)smem + LSTM_BYTES, 3, tid, wb, mb);
        return;
    }

    // ===================== CRITICAL: recurrent LSTM ====================
    const int ct = tid - 256;
    uint32_t* sH32 = (uint32_t*)smem;                    // [k 0..511][40]
    uint32_t* sW32 = (uint32_t*)smem + SH32_U32;         // [j 0..15][516]
    float*    sRed = smem + SH32_U32 + SW32_U32;         // [par][s][b*20+j]

    const int L0 = blockIdx.x * 4;

    // ---- build pair-duplicated fp16 Wh slice once ----
    for (int it = ct; it < 16 * 512; it += 256) {
        int k = it >> 4;
        int j = it & 15;
        int g = j >> 2, jl = j & 3;
        float w;
        if (g < 3) w = ww[(size_t)(512 + k) * GW + g * 512 + L0 + jl];
        else       w = mw[(size_t)(512 + k) * L_ + L0 + jl];
        unsigned hw = (unsigned)__half_as_ushort(__float2half_rn(w));
        sW32[j * 516 + k] = hw | (hw << 16);
    }

    const int s  = ct >> 5;             // K chunk 0..7 (k32 in [s*64, s*64+64))
    const int u  = ct & 31;
    const int l4 = u >> 2;              // 0..7
    const int u3 = u & 3;               // 0..3
    const int kbase = s * 64;

    const int eb  = ct >> 2;
    const int ejl = ct & 3;
    float c_reg = 0.f;
    float pre_r[4];
    if (ct < 128) {
        c_reg = c0[eb * L_ + L0 + ejl];
        g_hbuf[(L0 + ejl) * 32 + eb] = pack_hilo(h0[eb * L_ + L0 + ejl]);
    }
    BARC(2, 256);
    if (ct == 0) st_rel(&g_flags[blockIdx.x * 8], 1u);

    if (ct < 128) {
        while (ld_acq(&g_windone[0]) < WIN_TILES) { }
        #pragma unroll
        for (int g = 0; g < 4; g++)
            pre_r[g] = g_pre[(size_t)eb * T_ * NG + g * 512 + L0 + ejl];
    }

    float* hid  = out;
    float* cell = out + (size_t)B_ * T_ * L_;

    const unsigned* myflag = &g_flags[(s * 16 + (u & 15)) * 8];

    int par = 0;
    for (int t = 0; t < T_; t++) {
        // ---- per-warp: wait for my 16 producers, stage my 64-k h block ----
        {
            const unsigned tgt = (unsigned)(t + 1);
            for (;;) {
                unsigned v = ld_acq(myflag);
                if (__all_sync(0xffffffffu, v >= tgt)) break;
            }
            const unsigned* buf = g_hbuf + (size_t)(t & 1) * (L_ * 32);
            #pragma unroll
            for (int qq = 0; qq < 16; qq++) {
                int f = qq * 32 + u;
                int krow = kbase + (f >> 3);
                int c4 = (f & 7) * 4;
                uint4 v4 = *(const uint4*)&buf[krow * 32 + c4];
                *(uint4*)&sH32[krow * 40 + c4] = v4;
            }
            __syncwarp();
        }

        // ---- h-part GEMM: fp16 HMMA, K' = 1024 (packed hi/lo), 32 MMAs ----
        float acc[2][2][4];                // [mt][nt][reg]
        #pragma unroll
        for (int mt = 0; mt < 2; mt++)
            #pragma unroll
            for (int nt = 0; nt < 2; nt++)
                #pragma unroll
                for (int r = 0; r < 4; r++) acc[mt][nt][r] = 0.f;

        #pragma unroll
        for (int kt = 0; kt < 8; kt++) {
            const int k32 = kbase + kt * 8 + u3;
            uint32_t bf[2][2];
            #pragma unroll
            for (int nt = 0; nt < 2; nt++) {
                bf[nt][0] = sW32[(nt * 8 + l4) * 516 + k32];
                bf[nt][1] = sW32[(nt * 8 + l4) * 516 + k32 + 4];
            }
            #pragma unroll
            for (int mt = 0; mt < 2; mt++) {
                const int r = mt * 16 + l4;
                uint32_t af[4];
                af[0] = sH32[k32 * 40 + r];
                af[1] = sH32[k32 * 40 + r + 8];
                af[2] = sH32[(k32 + 4) * 40 + r];
                af[3] = sH32[(k32 + 4) * 40 + r + 8];
                #pragma unroll
                for (int nt = 0; nt < 2; nt++)
                    mma16816h(acc[mt][nt], af, bf[nt]);
            }
        }

        float* red = sRed + par * (8 * 640) + s * 640;
        #pragma unroll
        for (int mt = 0; mt < 2; mt++) {
            const int b1 = mt * 16 + l4;
            #pragma unroll
            for (int nt = 0; nt < 2; nt++) {
                const int jc = nt * 8 + u3 * 2;
                *(float2*)&red[b1 * 20 + jc]       = make_float2(acc[mt][nt][0], acc[mt][nt][1]);
                *(float2*)&red[(b1 + 8) * 20 + jc] = make_float2(acc[mt][nt][2], acc[mt][nt][3]);
            }
        }
        BARC(2, 256);

        // ---- reduce K chunks + gate epilogue + publish h(t+1) ----
        if (ct < 128) {
            float* redP = sRed + par * (8 * 640);
            float z[4];
            #pragma unroll
            for (int g = 0; g < 4; g++) {
                float v = 0.f;
                #pragma unroll
                for (int ss = 0; ss < 8; ss++)
                    v += redP[ss * 640 + eb * 20 + g * 4 + ejl];
                z[g] = v + pre_r[g];
            }
            float ig = sigf(z[0]);
            float fg = sigf(z[1]);
            float og = sigf(z[2]);
            float mg = tanh_fast(z[3]);
            c_reg = fg * c_reg + ig * mg;
            float hn = og * tanh_fast(c_reg);
            size_t off = ((size_t)eb * T_ + t) * L_ + L0 + ejl;
            if (t + 1 < T_) {
                unsigned* nb = g_hbuf + (size_t)((t + 1) & 1) * (L_ * 32);
                nb[(L0 + ejl) * 32 + eb] = pack_hilo(hn);
                BARC(1, 128);
                if (ct == 0)
                    st_rel(&g_flags[blockIdx.x * 8], (unsigned)(t + 2));
                hid[off]  = hn;
                cell[off] = c_reg;
                if (((t + 1) & 127) == 0) {
                    const unsigned* wd = &g_windone[(t + 1) >> 7];
                    while (ld_acq(wd) < WIN_TILES) { }
                }
                #pragma unroll
                for (int g = 0; g < 4; g++)
                    pre_r[g] = g_pre[((size_t)eb * T_ + (t + 1)) * NG + g * 512 + L0 + ejl];
            } else {
                hid[off]  = hn;
                cell[off] = c_reg;
            }
        }
        par ^= 1;
    }
}

// ---------------------------------------------------------------------------
extern "C" void kernel_launch(void* const* d_in, const int* in_sizes, int n_in,
                              void* d_out, int out_size)
{
    const float* x  = (const float*)d_in[0];
    const float* h0 = (const float*)d_in[1];
    const float* c0 = (const float*)d_in[2];
    const float* ww = (const float*)d_in[3];
    const float* wb = (const float*)d_in[4];
    const float* mw = (const float*)d_in[5];
    const float* mb = (const float*)d_in[6];
    float* out = (float*)d_out;

    cudaFuncSetAttribute(fused_kernel,
                         cudaFuncAttributeMaxDynamicSharedMemorySize, SMEM_TOTAL);

    conv_kernel<<<32768, 256>>>(x, ww, mw);
    fused_kernel<<<GRID, 512, SMEM_TOTAL>>>(h0, c0, ww, wb, mw, mb, out);
}